// round 4
// baseline (speedup 1.0000x reference)
#include <cuda_runtime.h>

// CLUBv2: mi = BETA * sum_d Var_d(y[:, d])
// y: [1024, 256] fp32 row-major. Output: 1 fp32 scalar.
//
//   mi = ( (sum_all y^2)/N - sum_d mu_d^2 ) * BETA
//
// S (per-column sums): 2^26 fixed-point int64 relaxed REDs, exactly
// associative -> deterministic. Q: single grand-total scalar (one RED per
// warp after shuffle-reduce). Ticket is per-WARP with acq_rel: no block
// barriers anywhere. Winner warp alone does the 2KB tail.

#define N_ROWS 1024
#define N_COLS 256
#define GRID   32
#define ROWS_PER_BLOCK (N_ROWS / GRID)       // 32
#define TOTAL_WARPS    (GRID * (N_COLS/32))  // 256
#define BETA_F 0.001f
#define FIX_SCALE 67108864.0f                // 2^26
#define FIX_INV   (1.0f / 67108864.0f)

__device__ long long    g_S[N_COLS];   // fixed-point column sums
__device__ long long    g_Qtot;        // fixed-point grand sum of squares
__device__ unsigned int g_ticket = 0;
// All scratch starts zeroed; winner warp re-zeros after consuming ->
// every graph replay sees zeros. Deterministic.

__device__ __forceinline__ unsigned int atom_add_acq_rel(unsigned int* addr,
                                                         unsigned int v) {
    unsigned int old;
    asm volatile("atom.acq_rel.gpu.global.add.u32 %0, [%1], %2;"
                 : "=r"(old) : "l"(addr), "r"(v) : "memory");
    return old;
}

__global__ void __launch_bounds__(N_COLS, 1)
club_var_kernel(const float* __restrict__ y, float* __restrict__ out) {
    const int t    = threadIdx.x;        // column index 0..255
    const int b    = blockIdx.x;
    const int lane = t & 31;

    // Phase 1: 32 rows per block per column, coalesced, high MLP.
    float s = 0.0f, q = 0.0f;
    const float* p = y + (size_t)b * ROWS_PER_BLOCK * N_COLS + t;
    #pragma unroll
    for (int r = 0; r < ROWS_PER_BLOCK; ++r) {
        float v = p[r * N_COLS];
        s += v;
        q = fmaf(v, v, q);
    }

    // Per-column S: one relaxed int64 RED per thread.
    atomicAdd((unsigned long long*)&g_S[t],
              (unsigned long long)(long long)llrintf(s * FIX_SCALE));

    // Q grand total: warp shuffle-reduce (fixed order -> deterministic).
    #pragma unroll
    for (int off = 16; off > 0; off >>= 1)
        q += __shfl_down_sync(0xFFFFFFFFu, q, off);

    // Warp-granular ticket. syncwarp orders all lanes' REDs before lane0's
    // release; acq_rel ticket publishes them and acquires everyone else's.
    __syncwarp();
    unsigned int old = 0;
    if (lane == 0) {
        atomicAdd((unsigned long long*)&g_Qtot,
                  (unsigned long long)(long long)llrintf(q * FIX_SCALE));
        old = atom_add_acq_rel(&g_ticket, 1u);
    }
    old = __shfl_sync(0xFFFFFFFFu, old, 0);

    if (old == (unsigned)(TOTAL_WARPS - 1)) {
        __syncwarp();   // extend lane0's acquire to all lanes (hb chain)

        // Tail: winner warp loads 256 int64 partials (2KB) coalesced.
        // lane owns columns 8*lane .. 8*lane+7 = longlong2 indices 4l..4l+3.
        const longlong2* ps = (const longlong2*)g_S;
        longlong2 v0 = __ldcg(&ps[4 * lane + 0]);
        longlong2 v1 = __ldcg(&ps[4 * lane + 1]);
        longlong2 v2 = __ldcg(&ps[4 * lane + 2]);
        longlong2 v3 = __ldcg(&ps[4 * lane + 3]);
        long long Qf = (lane == 0) ? __ldcg(&g_Qtot) : 0;

        // Reset scratch for the next graph replay (fire-and-forget).
        longlong2 z; z.x = 0; z.y = 0;
        ((longlong2*)g_S)[4 * lane + 0] = z;
        ((longlong2*)g_S)[4 * lane + 1] = z;
        ((longlong2*)g_S)[4 * lane + 2] = z;
        ((longlong2*)g_S)[4 * lane + 3] = z;

        const float invN = 1.0f / (float)N_ROWS;
        const float k = FIX_INV * invN;          // fixed -> mu in one mul
        float m, acc = 0.0f;
        m = (float)v0.x * k; acc = fmaf(m, m, acc);
        m = (float)v0.y * k; acc = fmaf(m, m, acc);
        m = (float)v1.x * k; acc = fmaf(m, m, acc);
        m = (float)v1.y * k; acc = fmaf(m, m, acc);
        m = (float)v2.x * k; acc = fmaf(m, m, acc);
        m = (float)v2.y * k; acc = fmaf(m, m, acc);
        m = (float)v3.x * k; acc = fmaf(m, m, acc);
        m = (float)v3.y * k; acc = fmaf(m, m, acc);

        // acc now holds this lane's sum of mu_d^2; reduce across warp.
        #pragma unroll
        for (int off = 16; off > 0; off >>= 1)
            acc += __shfl_down_sync(0xFFFFFFFFu, acc, off);

        if (lane == 0) {
            float EQ = (float)Qf * FIX_INV * invN;   // sum_d E[y^2]_d
            out[0] = (EQ - acc) * BETA_F;
            g_Qtot   = 0;
            g_ticket = 0;
        }
    }
}

extern "C" void kernel_launch(void* const* d_in, const int* in_sizes, int n_in,
                              void* d_out, int out_size) {
    (void)in_sizes; (void)n_in; (void)out_size;
    const float* y = (const float*)d_in[0];
    float* out = (float*)d_out;
    club_var_kernel<<<GRID, N_COLS>>>(y, out);
}